// round 16
// baseline (speedup 1.0000x reference)
#include <cuda_runtime.h>

#define B_     2
#define N_IN_  262144
#define D_     32
#define N_OUT_ 65536
#define K_     4
#define NK_    9
#define TOTAL_ (B_ * N_OUT_ * K_)   // 524288 outputs

// sigma-dedup results + interleaved coords
__device__ float  g_uc0;              // 1/(2*sigma^2) when uniform
__device__ int    g_u;                // 1 = uniform sigma, 2 = general
__device__ float2 g_c2[B_ * N_IN_];   // (cx, cy) per input point

// Minimal prep: one point per thread, fully coalesced.
__global__ void __launch_bounds__(256) prep_kernel(
    const float* __restrict__ sigma, const float* __restrict__ cin)
{
    const int tid = blockIdx.x * blockDim.x + threadIdx.x;

    if (blockIdx.x == 0 && threadIdx.x < 32) {
        float s = sigma[threadIdx.x];
        float c = 1.0f / (2.0f * s * s);
        float c0 = __shfl_sync(0xffffffffu, c, 0);
        unsigned same = __ballot_sync(0xffffffffu, c == c0);
        if (threadIdx.x == 0) {
            g_u   = (same == 0xffffffffu) ? 1 : 2;
            g_uc0 = c0;
        }
    }

    if (tid < B_ * N_IN_) {
        float cx = __ldg(&cin[tid]);
        float cy = __ldg(&cin[B_ * N_IN_ + tid]);
        g_c2[tid] = make_float2(cx, cy);
    }
}

// ---------------- uniform-sigma hot kernel ----------------
// Warp = 4 outputs. Coord/exp front-end identical to R15 (lanes 0..17).
// Accumulate phase: lane = channel; each (g, j) gather is ONE 128B line
// loaded by all 32 lanes (cross-LDG wavefront rate, no within-LDG replays).
__global__ void __launch_bounds__(256) proj_uniform_kernel(
    const float* __restrict__ x,      // (B, N_IN, D)
    const float* __restrict__ cout,   // (2, B, N_OUT, K)
    const int*   __restrict__ nidx,   // (B, N_OUT, K, NK)
    float* __restrict__ out)          // (B, N_OUT*K, D)
{
    if (g_u != 1) return;

    const unsigned lane = threadIdx.x & 31u;
    const int w    = (int)((blockIdx.x * (unsigned)blockDim.x + threadIdx.x) >> 5);
    const int bnk0 = w * 4;
    const int b    = bnk0 >> 18;

    // lanes 0..17: (output o, neighbor j), phases A (outputs 0,1) / B (2,3)
    int   idxA = 0, idxB = 0;
    float tA = 0.0f, tB = 0.0f;
    if (lane < 2 * NK_) {
        const int o = (lane >= NK_) ? 1 : 0;
        const int j = (int)lane - o * NK_;

        const int oA = bnk0 + o;
        idxA = __ldg(&nidx[(size_t)oA * NK_ + j]);
        const int oB = bnk0 + 2 + o;
        idxB = __ldg(&nidx[(size_t)oB * NK_ + j]);

        float2 cA = g_c2[b * N_IN_ + idxA];
        float2 cB = g_c2[b * N_IN_ + idxB];
        float oxA = __ldg(&cout[oA]);
        float oyA = __ldg(&cout[oA + TOTAL_]);
        float oxB = __ldg(&cout[oB]);
        float oyB = __ldg(&cout[oB + TOTAL_]);

        float dxA = oxA - cA.x, dyA = oyA - cA.y;
        float dxB = oxB - cB.x, dyB = oyB - cB.y;
        tA = -(dxA * dxA + dyA * dyA);
        tB = -(dxB * dxB + dyB * dyB);
    }

    // 2 MUFU passes warp-wide cover all 36 weights
    float eA = __expf(tA * g_uc0);
    float eB = __expf(tB * g_uc0);

    // lane = channel; one row (one line) per LDG
    const float* xb = x + (size_t)b * N_IN_ * D_ + lane;

#pragma unroll
    for (int g = 0; g < 4; g++) {
        const int selbase = (g & 1) * NK_;

        // broadcast the 9 neighbor row ids for output g (uniform across warp)
        int ij[NK_];
#pragma unroll
        for (int j = 0; j < NK_; j++) {
            int a  = __shfl_sync(0xffffffffu, idxA, selbase + j);
            int bb = __shfl_sync(0xffffffffu, idxB, selbase + j);
            ij[j] = (g < 2) ? a : bb;
        }

        // 9 single-line gathers, batched (MLP = 9)
        float v[NK_];
#pragma unroll
        for (int j = 0; j < NK_; j++)
            v[j] = __ldg(xb + (size_t)ij[j] * D_);

        // weights + accumulate this output's channel
        float acc = 0.0f, den = 1e-9f;
#pragma unroll
        for (int j = 0; j < NK_; j++) {
            float ea = __shfl_sync(0xffffffffu, eA, selbase + j);
            float eb = __shfl_sync(0xffffffffu, eB, selbase + j);
            float wj = (g < 2) ? ea : eb;
            acc = fmaf(wj, v[j], acc);
            den += wj;
        }
        out[(size_t)(bnk0 + g) * D_ + lane] = acc * __fdividef(1.0f, den);
    }
}

// ---------------- general-sigma fallback: grid-strided, dead when uniform ---
__global__ void __launch_bounds__(256) proj_general_kernel(
    const float* __restrict__ x,
    const float* __restrict__ cout,
    const float* __restrict__ sigma,
    const int*   __restrict__ nidx,
    float* __restrict__ out)
{
    if (g_u == 1) return;

    const unsigned lane = threadIdx.x & 31u;
    const int nwarps_total = TOTAL_ / 4;
    const int warps_per_grid = (int)((gridDim.x * blockDim.x) >> 5);

    for (int w = (int)((blockIdx.x * (unsigned)blockDim.x + threadIdx.x) >> 5);
         w < nwarps_total; w += warps_per_grid) {
        const int bnk0 = w * 4;
        const int g    = (int)(lane >> 3);
        const int sl   = (int)(lane & 7u);
        const int bnk  = bnk0 + g;
        const int b    = bnk0 >> 18;

        int   idxA = 0, idxB = 0;
        float tA = 0.0f, tB = 0.0f;
        if (lane < 2 * NK_) {
            const int o = (lane >= NK_) ? 1 : 0;
            const int j = (int)lane - o * NK_;
            const int oA = bnk0 + o;
            idxA = __ldg(&nidx[(size_t)oA * NK_ + j]);
            const int oB = bnk0 + 2 + o;
            idxB = __ldg(&nidx[(size_t)oB * NK_ + j]);
            float2 cA = g_c2[b * N_IN_ + idxA];
            float2 cB = g_c2[b * N_IN_ + idxB];
            float oxA = __ldg(&cout[oA]);
            float oyA = __ldg(&cout[oA + TOTAL_]);
            float oxB = __ldg(&cout[oB]);
            float oyB = __ldg(&cout[oB + TOTAL_]);
            float dxA = oxA - cA.x, dyA = oyA - cA.y;
            float dxB = oxB - cB.x, dyB = oyB - cB.y;
            tA = -(dxA * dxA + dyA * dyA);
            tB = -(dxB * dxB + dyB * dyB);
        }

        const int selbase = (g & 1) * NK_;
        int ij[NK_];
#pragma unroll
        for (int j = 0; j < NK_; j++) {
            int a  = __shfl_sync(0xffffffffu, idxA, selbase + j);
            int bb = __shfl_sync(0xffffffffu, idxB, selbase + j);
            ij[j] = (g < 2) ? a : bb;
        }

        const float4* xb = (const float4*)(x + (size_t)b * N_IN_ * D_) + sl;
        float4 f[NK_];
#pragma unroll
        for (int j = 0; j < NK_; j++) f[j] = __ldg(xb + (size_t)ij[j] * (D_ / 4));

        float4 s4 = ((const float4*)sigma)[sl];
        float c0 = 1.0f / (2.0f * s4.x * s4.x);
        float c1 = 1.0f / (2.0f * s4.y * s4.y);
        float c2 = 1.0f / (2.0f * s4.z * s4.z);
        float c3 = 1.0f / (2.0f * s4.w * s4.w);
        float4 num = make_float4(0.f, 0.f, 0.f, 0.f);
        float d0 = 1e-9f, d1 = 1e-9f, d2 = 1e-9f, d3 = 1e-9f;
#pragma unroll
        for (int j = 0; j < NK_; j++) {
            float ta = __shfl_sync(0xffffffffu, tA, selbase + j);
            float tb = __shfl_sync(0xffffffffu, tB, selbase + j);
            float tv = (g < 2) ? ta : tb;
            float w0 = __expf(tv * c0);
            float w1 = __expf(tv * c1);
            float w2 = __expf(tv * c2);
            float w3 = __expf(tv * c3);
            num.x = fmaf(w0, f[j].x, num.x);
            num.y = fmaf(w1, f[j].y, num.y);
            num.z = fmaf(w2, f[j].z, num.z);
            num.w = fmaf(w3, f[j].w, num.w);
            d0 += w0; d1 += w1; d2 += w2; d3 += w3;
        }
        float4 r = make_float4(__fdividef(num.x, d0), __fdividef(num.y, d1),
                               __fdividef(num.z, d2), __fdividef(num.w, d3));
        ((float4*)(out + (size_t)bnk * D_))[sl] = r;
    }
}

extern "C" void kernel_launch(void* const* d_in, const int* in_sizes, int n_in,
                              void* d_out, int out_size) {
    const float* x     = (const float*)d_in[0];
    const float* cin   = (const float*)d_in[1];
    const float* cout  = (const float*)d_in[2];
    const float* sigma = (const float*)d_in[3];
    const int*   nidx  = (const int*)d_in[4];
    float* out = (float*)d_out;

    prep_kernel<<<(B_ * N_IN_ + 255) / 256, 256>>>(sigma, cin);

    // hot path: 4 outputs/warp -> 131072 warps -> 16384 blocks
    proj_uniform_kernel<<<TOTAL_ / 4 / 8, 256>>>(x, cout, nidx, out);
    // fallback: grid-strided; negligible dead cost when sigma uniform
    proj_general_kernel<<<296, 256>>>(x, cout, sigma, nidx, out);
}

// round 17
// speedup vs baseline: 1.2346x; 1.2346x over previous
#include <cuda_runtime.h>

#define B_     2
#define N_IN_  262144
#define D_     32
#define N_OUT_ 65536
#define K_     4
#define NK_    9
#define TOTAL_ (B_ * N_OUT_ * K_)   // 524288 outputs

// sigma-dedup results + interleaved coords
__device__ float  g_uc0;              // 1/(2*sigma^2) when uniform
__device__ int    g_u;                // 1 = uniform sigma, 2 = general
__device__ float2 g_c2[B_ * N_IN_];   // (cx, cy) per input point

// Minimal prep: one point per thread, fully coalesced.
__global__ void __launch_bounds__(256) prep_kernel(
    const float* __restrict__ sigma, const float* __restrict__ cin)
{
    const int tid = blockIdx.x * blockDim.x + threadIdx.x;

    if (blockIdx.x == 0 && threadIdx.x < 32) {
        float s = sigma[threadIdx.x];
        float c = 1.0f / (2.0f * s * s);
        float c0 = __shfl_sync(0xffffffffu, c, 0);
        unsigned same = __ballot_sync(0xffffffffu, c == c0);
        if (threadIdx.x == 0) {
            g_u   = (same == 0xffffffffu) ? 1 : 2;
            g_uc0 = c0;
        }
    }

    if (tid < B_ * N_IN_) {
        float cx = __ldg(&cin[tid]);
        float cy = __ldg(&cin[B_ * N_IN_ + tid]);
        g_c2[tid] = make_float2(cx, cy);
    }
}

// ---------------- uniform-sigma hot kernel ----------------
// Warp = 4 outputs; g = lane>>3 (output), sl = lane&7 (channel quad).
// R15 body with ONE change: ALL loads (idx, coords, cout, 9 feature gathers)
// are issued before any coord consumption — d2/exp deferred until after the
// feature-gather batch so the coord and feature latencies overlap.
__global__ void __launch_bounds__(256) proj_uniform_kernel(
    const float* __restrict__ x,      // (B, N_IN, D)
    const float* __restrict__ cout,   // (2, B, N_OUT, K)
    const int*   __restrict__ nidx,   // (B, N_OUT, K, NK)
    float* __restrict__ out)          // (B, N_OUT*K, D)
{
    if (g_u != 1) return;

    const unsigned lane = threadIdx.x & 31u;
    const int w    = (int)((blockIdx.x * (unsigned)blockDim.x + threadIdx.x) >> 5);
    const int bnk0 = w * 4;
    const int g    = (int)(lane >> 3);
    const int sl   = (int)(lane & 7u);
    const int bnk  = bnk0 + g;
    const int b    = bnk0 >> 18;

    // ---- load phase: everything issued, nothing consumed ----
    int    idxA = 0, idxB = 0;
    float2 cA = make_float2(0.f, 0.f), cB = make_float2(0.f, 0.f);
    float  oxA = 0.f, oyA = 0.f, oxB = 0.f, oyB = 0.f;
    if (lane < 2 * NK_) {
        const int o = (lane >= NK_) ? 1 : 0;
        const int j = (int)lane - o * NK_;

        const int oA = bnk0 + o;
        const int oB = bnk0 + 2 + o;
        idxA = __ldg(&nidx[(size_t)oA * NK_ + j]);
        idxB = __ldg(&nidx[(size_t)oB * NK_ + j]);

        cA = g_c2[b * N_IN_ + idxA];
        cB = g_c2[b * N_IN_ + idxB];
        oxA = __ldg(&cout[oA]);
        oyA = __ldg(&cout[oA + TOTAL_]);
        oxB = __ldg(&cout[oB]);
        oyB = __ldg(&cout[oB + TOTAL_]);
    }

    // idx broadcast (independent of coord results), then batched gathers
    const int selbase = (g & 1) * NK_;
    int ij[NK_];
#pragma unroll
    for (int j = 0; j < NK_; j++) {
        int a  = __shfl_sync(0xffffffffu, idxA, selbase + j);
        int bb = __shfl_sync(0xffffffffu, idxB, selbase + j);
        ij[j] = (g < 2) ? a : bb;
    }

    const float4* xb = (const float4*)(x + (size_t)b * N_IN_ * D_) + sl;
    float4 f[NK_];
#pragma unroll
    for (int j = 0; j < NK_; j++) f[j] = __ldg(xb + (size_t)ij[j] * (D_ / 4));

    // ---- consume phase: d2 + exp now (coord latency overlapped w/ gathers) ----
    float tA = 0.0f, tB = 0.0f;
    if (lane < 2 * NK_) {
        float dxA = oxA - cA.x, dyA = oyA - cA.y;
        float dxB = oxB - cB.x, dyB = oyB - cB.y;
        tA = -(dxA * dxA + dyA * dyA);
        tB = -(dxB * dxB + dyB * dyB);
    }
    float eA = __expf(tA * g_uc0);
    float eB = __expf(tB * g_uc0);

    float4 num = make_float4(0.f, 0.f, 0.f, 0.f);
    float den = 1e-9f;
#pragma unroll
    for (int j = 0; j < NK_; j++) {
        float ea = __shfl_sync(0xffffffffu, eA, selbase + j);
        float eb = __shfl_sync(0xffffffffu, eB, selbase + j);
        float wj = (g < 2) ? ea : eb;
        num.x = fmaf(wj, f[j].x, num.x);
        num.y = fmaf(wj, f[j].y, num.y);
        num.z = fmaf(wj, f[j].z, num.z);
        num.w = fmaf(wj, f[j].w, num.w);
        den += wj;
    }
    float inv = __fdividef(1.0f, den);
    float4 r = make_float4(num.x * inv, num.y * inv, num.z * inv, num.w * inv);
    ((float4*)(out + (size_t)bnk * D_))[sl] = r;
}

// ---------------- general-sigma fallback: grid-strided, dead when uniform ---
__global__ void __launch_bounds__(256) proj_general_kernel(
    const float* __restrict__ x,
    const float* __restrict__ cout,
    const float* __restrict__ sigma,
    const int*   __restrict__ nidx,
    float* __restrict__ out)
{
    if (g_u == 1) return;

    const unsigned lane = threadIdx.x & 31u;
    const int nwarps_total = TOTAL_ / 4;
    const int warps_per_grid = (int)((gridDim.x * blockDim.x) >> 5);

    for (int w = (int)((blockIdx.x * (unsigned)blockDim.x + threadIdx.x) >> 5);
         w < nwarps_total; w += warps_per_grid) {
        const int bnk0 = w * 4;
        const int g    = (int)(lane >> 3);
        const int sl   = (int)(lane & 7u);
        const int bnk  = bnk0 + g;
        const int b    = bnk0 >> 18;

        int   idxA = 0, idxB = 0;
        float tA = 0.0f, tB = 0.0f;
        if (lane < 2 * NK_) {
            const int o = (lane >= NK_) ? 1 : 0;
            const int j = (int)lane - o * NK_;
            const int oA = bnk0 + o;
            idxA = __ldg(&nidx[(size_t)oA * NK_ + j]);
            const int oB = bnk0 + 2 + o;
            idxB = __ldg(&nidx[(size_t)oB * NK_ + j]);
            float2 cA = g_c2[b * N_IN_ + idxA];
            float2 cB = g_c2[b * N_IN_ + idxB];
            float oxA = __ldg(&cout[oA]);
            float oyA = __ldg(&cout[oA + TOTAL_]);
            float oxB = __ldg(&cout[oB]);
            float oyB = __ldg(&cout[oB + TOTAL_]);
            float dxA = oxA - cA.x, dyA = oyA - cA.y;
            float dxB = oxB - cB.x, dyB = oyB - cB.y;
            tA = -(dxA * dxA + dyA * dyA);
            tB = -(dxB * dxB + dyB * dyB);
        }

        const int selbase = (g & 1) * NK_;
        int ij[NK_];
#pragma unroll
        for (int j = 0; j < NK_; j++) {
            int a  = __shfl_sync(0xffffffffu, idxA, selbase + j);
            int bb = __shfl_sync(0xffffffffu, idxB, selbase + j);
            ij[j] = (g < 2) ? a : bb;
        }

        const float4* xb = (const float4*)(x + (size_t)b * N_IN_ * D_) + sl;
        float4 f[NK_];
#pragma unroll
        for (int j = 0; j < NK_; j++) f[j] = __ldg(xb + (size_t)ij[j] * (D_ / 4));

        float4 s4 = ((const float4*)sigma)[sl];
        float c0 = 1.0f / (2.0f * s4.x * s4.x);
        float c1 = 1.0f / (2.0f * s4.y * s4.y);
        float c2 = 1.0f / (2.0f * s4.z * s4.z);
        float c3 = 1.0f / (2.0f * s4.w * s4.w);
        float4 num = make_float4(0.f, 0.f, 0.f, 0.f);
        float d0 = 1e-9f, d1 = 1e-9f, d2 = 1e-9f, d3 = 1e-9f;
#pragma unroll
        for (int j = 0; j < NK_; j++) {
            float ta = __shfl_sync(0xffffffffu, tA, selbase + j);
            float tb = __shfl_sync(0xffffffffu, tB, selbase + j);
            float tv = (g < 2) ? ta : tb;
            float w0 = __expf(tv * c0);
            float w1 = __expf(tv * c1);
            float w2 = __expf(tv * c2);
            float w3 = __expf(tv * c3);
            num.x = fmaf(w0, f[j].x, num.x);
            num.y = fmaf(w1, f[j].y, num.y);
            num.z = fmaf(w2, f[j].z, num.z);
            num.w = fmaf(w3, f[j].w, num.w);
            d0 += w0; d1 += w1; d2 += w2; d3 += w3;
        }
        float4 r = make_float4(__fdividef(num.x, d0), __fdividef(num.y, d1),
                               __fdividef(num.z, d2), __fdividef(num.w, d3));
        ((float4*)(out + (size_t)bnk * D_))[sl] = r;
    }
}

extern "C" void kernel_launch(void* const* d_in, const int* in_sizes, int n_in,
                              void* d_out, int out_size) {
    const float* x     = (const float*)d_in[0];
    const float* cin   = (const float*)d_in[1];
    const float* cout  = (const float*)d_in[2];
    const float* sigma = (const float*)d_in[3];
    const int*   nidx  = (const int*)d_in[4];
    float* out = (float*)d_out;

    prep_kernel<<<(B_ * N_IN_ + 255) / 256, 256>>>(sigma, cin);

    // hot path: 4 outputs/warp -> 131072 warps -> 16384 blocks
    proj_uniform_kernel<<<TOTAL_ / 4 / 8, 256>>>(x, cout, nidx, out);
    // fallback: grid-strided; negligible dead cost when sigma uniform
    proj_general_kernel<<<148, 256>>>(x, cout, sigma, nidx, out);
}